// round 6
// baseline (speedup 1.0000x reference)
#include <cuda_runtime.h>
#include <math.h>

#define B_ 16
#define C_ 64
#define H_ 192
#define W_ 192
#define R_ 64

// ---------------- scratch (device globals; no allocation) ----------------
__device__ float g_cp[B_ * C_];            // [B][C]
__device__ float g_hp[B_ * H_];            // [B][H]
__device__ float g_wp[B_ * W_];            // [B][W]
__device__ float g_RS[B_ * C_ * H_];       // per-plane row sums  [B][C][H]
__device__ float g_CS[B_ * C_ * W_];       // per-plane col sums  [B][C][W]
__device__ float g_T [B_ * R_ * C_];       // p[r]*sigmoid(Cw)    [B][R][C]
__device__ float g_Hw[B_ * H_ * R_];       // sigmoid(Hw)         [B][H][R]
__device__ float g_Ww[B_ * R_ * W_];       // sigmoid(Ww)         [B][R][W]

// ---------------- f32x2 helpers (Blackwell packed fp32) -------------------
__device__ __forceinline__ unsigned long long pk2(float x, float y) {
    unsigned long long r;
    asm("mov.b64 %0, {%1, %2};" : "=l"(r) : "f"(x), "f"(y));
    return r;
}
__device__ __forceinline__ void fma2(unsigned long long& d,
                                     unsigned long long a,
                                     unsigned long long b) {
    asm("fma.rn.f32x2 %0, %1, %2, %3;" : "=l"(d) : "l"(a), "l"(b), "l"(d));
}
__device__ __forceinline__ float2 upk2(unsigned long long v) {
    float2 f;
    asm("mov.b64 {%0, %1}, %2;" : "=f"(f.x), "=f"(f.y) : "l"(v));
    return f;
}

__device__ __forceinline__ float sigmoidf_(float x) {
    return 1.0f / (1.0f + expf(-x));
}

// Multi-value butterfly: reduce acc[0..15] (one per batch) across 32 lanes
// with 16 shfls. Afterwards every lane holds in acc[0] the full sum for
// batch (lane>>1)&15; even lanes are the designated writers.
__device__ __forceinline__ void butterfly16(float (&acc)[B_], int lane) {
    #pragma unroll
    for (int off = 16; off >= 2; off >>= 1) {
        const int nv = off >> 1;
        const bool hi = (lane & off) != 0;
        #pragma unroll
        for (int j = 0; j < nv; j++) {
            float send = hi ? acc[j] : acc[j + nv];
            float recv = __shfl_xor_sync(0xffffffffu, send, off);
            acc[j] = (hi ? acc[j + nv] : acc[j]) + recv;
        }
    }
    acc[0] += __shfl_xor_sync(0xffffffffu, acc[0], 1);
}

// ---------------- kernel 1: per-plane pools ------------------------------
__global__ void __launch_bounds__(192) pool_kernel(const float* __restrict__ X) {
    const int c = blockIdx.x;
    const int b = blockIdx.y;
    const float* plane = X + ((b * C_ + c) * H_) * (long)W_;

    const int tid  = threadIdx.x;
    const int warp = tid >> 5;
    const int lane = tid & 31;

    __shared__ float scs[6][W_];
    __shared__ float swt[6];

    float col0 = 0.f, col1 = 0.f, col2 = 0.f, col3 = 0.f, col4 = 0.f, col5 = 0.f;
    float tot = 0.f;

    const int h0 = warp * 32;
    for (int i = 0; i < 32; i++) {
        const int h = h0 + i;
        const float* row = plane + h * W_;
        float v0 = row[lane +   0];
        float v1 = row[lane +  32];
        float v2 = row[lane +  64];
        float v3 = row[lane +  96];
        float v4 = row[lane + 128];
        float v5 = row[lane + 160];
        col0 += v0; col1 += v1; col2 += v2; col3 += v3; col4 += v4; col5 += v5;
        float rs = ((v0 + v1) + (v2 + v3)) + (v4 + v5);
        #pragma unroll
        for (int off = 16; off >= 1; off >>= 1)
            rs += __shfl_down_sync(0xffffffffu, rs, off);
        if (lane == 0) {
            g_RS[(b * C_ + c) * H_ + h] = rs;
            tot += rs;
        }
    }
    scs[warp][lane +   0] = col0;
    scs[warp][lane +  32] = col1;
    scs[warp][lane +  64] = col2;
    scs[warp][lane +  96] = col3;
    scs[warp][lane + 128] = col4;
    scs[warp][lane + 160] = col5;
    if (lane == 0) swt[warp] = tot;
    __syncthreads();

    float cs = 0.f;
    #pragma unroll
    for (int j = 0; j < 6; j++) cs += scs[j][tid];
    g_CS[(b * C_ + c) * W_ + tid] = cs;

    if (tid == 0) {
        float t = 0.f;
        #pragma unroll
        for (int j = 0; j < 6; j++) t += swt[j];
        g_cp[b * C_ + c] = t * (1.0f / (H_ * (float)W_));
    }
}

// ---------------- kernel 2: reduce RS/CS over c -> hp, wp ----------------
__global__ void hw_pool_kernel() {
    const int i = blockIdx.x * blockDim.x + threadIdx.x;  // 0 .. B*H-1
    if (i >= B_ * H_) return;
    const int b = i / H_;
    const int h = i - b * H_;
    float s1 = 0.f, s2 = 0.f;
    for (int c = 0; c < C_; c++) {
        s1 += g_RS[(b * C_ + c) * H_ + h];
        s2 += g_CS[(b * C_ + c) * W_ + h];
    }
    g_hp[i] = s1 * (1.0f / (C_ * (float)W_));
    g_wp[i] = s2 * (1.0f / (C_ * (float)H_));
}

// ---------------- kernel 3: H/W sigmoid weights, warp-per-row GEMV -------
// blockIdx.y: 0 = H branch (Wh,bh -> g_Hw), 1 = W branch (Ww,bw -> g_Ww).
// Warp owns row m of the [12288 x 192] weight matrix; coalesced reads,
// 16-batch partials merged with a 16-shfl butterfly.
__global__ void __launch_bounds__(256) rhw_weights_kernel(
        const float* __restrict__ Wh, const float* __restrict__ bh,
        const float* __restrict__ Wwp, const float* __restrict__ bw) {
    const int tid  = threadIdx.x;
    const int warp = tid >> 5;
    const int lane = tid & 31;
    const int m    = blockIdx.x * 8 + warp;   // 0..12287
    const int r    = m / H_;
    const int d    = m - r * H_;
    const int wbranch = blockIdx.y;

    __shared__ float sp[B_][H_];
    {
        const float* pool = wbranch ? g_wp : g_hp;
        for (int i = tid; i < B_ * H_; i += 256)
            sp[i / H_][i - (i / H_) * H_] = pool[i];
    }
    __syncthreads();

    const float* Wsrc = wbranch ? Wwp : Wh;
    const float* bsrc = wbranch ? bw  : bh;
    const float* wrow = Wsrc + (long)m * H_;

    const float wv0 = wrow[lane +   0];
    const float wv1 = wrow[lane +  32];
    const float wv2 = wrow[lane +  64];
    const float wv3 = wrow[lane +  96];
    const float wv4 = wrow[lane + 128];
    const float wv5 = wrow[lane + 160];

    float acc[B_];
    #pragma unroll
    for (int b = 0; b < B_; b++) {
        float s = wv0 * sp[b][lane +   0];
        s = fmaf(wv1, sp[b][lane +  32], s);
        s = fmaf(wv2, sp[b][lane +  64], s);
        s = fmaf(wv3, sp[b][lane +  96], s);
        s = fmaf(wv4, sp[b][lane + 128], s);
        s = fmaf(wv5, sp[b][lane + 160], s);
        acc[b] = s;
    }
    butterfly16(acc, lane);

    if ((lane & 1) == 0) {
        const int batch = lane >> 1;
        const float v = sigmoidf_(acc[0] + bsrc[m]);
        if (wbranch == 0)
            g_Hw[(batch * H_ + d) * R_ + r] = v;      // [B][H][R]
        else
            g_Ww[(batch * R_ + r) * W_ + d] = v;      // [B][R][W]
    }
}

// ---------------- kernel 3c: T[b][r][c] = p[r]*sigmoid(Wc@cp+bc) ---------
__global__ void __launch_bounds__(256) cw_kernel(
        const float* __restrict__ Wc, const float* __restrict__ bc,
        const float* __restrict__ p) {
    const int tid  = threadIdx.x;
    const int warp = tid >> 5;
    const int lane = tid & 31;
    const int m    = blockIdx.x * 8 + warp;   // 0..4095
    const int r    = m / C_;
    const int d    = m - r * C_;

    __shared__ float sp[B_][C_];
    for (int i = tid; i < B_ * C_; i += 256)
        sp[i >> 6][i & 63] = g_cp[i];
    __syncthreads();

    const float* wrow = Wc + m * C_;
    const float wv0 = wrow[lane];
    const float wv1 = wrow[lane + 32];

    float acc[B_];
    #pragma unroll
    for (int b = 0; b < B_; b++)
        acc[b] = fmaf(wv1, sp[b][lane + 32], wv0 * sp[b][lane]);
    butterfly16(acc, lane);

    if ((lane & 1) == 0) {
        const int batch = lane >> 1;
        const float v = p[r] * sigmoidf_(acc[0] + bc[m]);
        g_T[(batch * R_ + r) * C_ + d] = v;           // [B][R][C]
    }
}

// ---------------- kernel 4: main fused GEMM + elementwise ----------------
// Block = (h, w-half, b). Smem: M[r][c] = T[b][r][c]*Hw[b][h][r] (64x64),
// V[r][w'] = Ww[b][r][half*96+w'] (64x96).
// Warp tile: 32 w (one per lane) x 32 c (16 f32x2 register pairs).
// Per r: 1 conflict-free LDS.32 (v) + 8 broadcast LDS.128 (M row) +
// 16 FFMA2 -> ~0.25 B LDS per FMA, FFMA2-pipe bound.
// Epilogue: w on lanes -> every LDG/STG is a full coalesced 128B line.
__global__ void __launch_bounds__(192) main_kernel(const float* __restrict__ X,
                                                   float* __restrict__ out) {
    const int h    = blockIdx.x;   // 0..191
    const int half = blockIdx.y;   // 0..1
    const int b    = blockIdx.z;   // 0..15

    const int tid   = threadIdx.x;
    const int warp  = tid >> 5;
    const int lane  = tid & 31;
    const int warpc = warp & 1;    // c half: 0 / 32
    const int warpw = warp >> 1;   // w tile: 0 / 32 / 64 (within 96)

    __shared__ float sM[R_ * C_];        // 16 KB  [r][c]
    __shared__ float sV[R_ * 96];        // 24 KB  [r][w']
    __shared__ float sh[R_];

    if (tid < R_) sh[tid] = g_Hw[(b * H_ + h) * R_ + tid];
    __syncthreads();

    // fill M = T * hw   (T layout [B][R][C], coalesced float4)
    {
        const float4* T4  = (const float4*)(g_T + b * (R_ * C_));
        float4*       sM4 = (float4*)sM;
        for (int i = tid; i < (R_ * C_) / 4; i += 192) {
            float4 t = T4[i];
            const float hv = sh[i >> 4];  // r = i / (C_/4)
            t.x *= hv; t.y *= hv; t.z *= hv; t.w *= hv;
            sM4[i] = t;
        }
    }
    // fill V half
    {
        float4* sV4 = (float4*)sV;
        for (int i = tid; i < R_ * 24; i += 192) {
            const int r = i / 24;
            const int j = i - r * 24;
            sV4[r * 24 + j] =
                ((const float4*)(g_Ww + (b * R_ + r) * W_ + half * 96))[j];
        }
    }
    __syncthreads();

    const ulonglong2* sM2 = (const ulonglong2*)sM;   // 16 per row of 64 floats
    const int vofs = warpw * 32 + lane;

    unsigned long long acc[16];   // c pairs: c = 32*warpc + 2j, 2j+1
    #pragma unroll
    for (int j = 0; j < 16; j++) acc[j] = 0ull;

    #pragma unroll 4
    for (int r = 0; r < R_; r++) {
        const float v = sV[r * 96 + vofs];
        const unsigned long long vv = pk2(v, v);
        #pragma unroll
        for (int j = 0; j < 8; j++) {
            const ulonglong2 m = sM2[r * 16 + warpc * 8 + j];  // 4 c-values
            fma2(acc[2 * j    ], m.x, vv);
            fma2(acc[2 * j + 1], m.y, vv);
        }
    }

    // epilogue: c0 = 32*warpc, w = half*96 + warpw*32 + lane (lane-coalesced)
    const int c0   = warpc * 32;
    const int base = ((b * C_ + c0) * H_ + h) * W_ + half * 96 + vofs;
    #pragma unroll
    for (int j = 0; j < 16; j++) {
        const float2 g = upk2(acc[j]);
        const int i0 = base + (2 * j) * (H_ * W_);
        const int i1 = i0 + H_ * W_;
        out[i0] = g.x * X[i0];
        out[i1] = g.y * X[i1];
    }
}

// ---------------- launch ---------------------------------------------------
extern "C" void kernel_launch(void* const* d_in, const int* in_sizes, int n_in,
                              void* d_out, int out_size) {
    const float* X   = (const float*)d_in[0];
    const float* p   = (const float*)d_in[1];
    const float* Wc  = (const float*)d_in[2];
    const float* bc  = (const float*)d_in[3];
    const float* Wh  = (const float*)d_in[4];
    const float* bh  = (const float*)d_in[5];
    const float* Wwp = (const float*)d_in[6];
    const float* bw  = (const float*)d_in[7];
    float* out = (float*)d_out;

    pool_kernel<<<dim3(C_, B_), 192>>>(X);
    hw_pool_kernel<<<(B_ * H_ + 255) / 256, 256>>>();
    cw_kernel<<<(R_ * C_) / 8, 256>>>(Wc, bc, p);
    rhw_weights_kernel<<<dim3((R_ * H_) / 8, 2), 256>>>(Wh, bh, Wwp, bw);
    main_kernel<<<dim3(H_, 2, B_), 192>>>(X, out);
}

// round 7
// speedup vs baseline: 1.2729x; 1.2729x over previous
#include <cuda_runtime.h>
#include <math.h>

#define B_ 16
#define C_ 64
#define H_ 192
#define W_ 192
#define R_ 64

// ---------------- scratch (device globals; no allocation) ----------------
__device__ float g_cp[B_ * C_];            // [B][C]
__device__ float g_hp[B_ * H_];            // [B][H]
__device__ float g_wp[B_ * W_];            // [B][W]
__device__ float g_RS[B_ * C_ * H_];       // per-plane row sums  [B][C][H]
__device__ float g_CS[B_ * C_ * W_];       // per-plane col sums  [B][C][W]
__device__ float g_T [B_ * R_ * C_];       // p[r]*sigmoid(Cw)    [B][R][C]
__device__ float g_Hw[B_ * H_ * R_];       // sigmoid(Hw)         [B][H][R]
__device__ float g_Ww[B_ * R_ * W_];       // sigmoid(Ww)         [B][R][W]

// ---------------- f32x2 helpers (Blackwell packed fp32) -------------------
__device__ __forceinline__ unsigned long long pk2(float x, float y) {
    unsigned long long r;
    asm("mov.b64 %0, {%1, %2};" : "=l"(r) : "f"(x), "f"(y));
    return r;
}
__device__ __forceinline__ void fma2(unsigned long long& d,
                                     unsigned long long a,
                                     unsigned long long b) {
    asm("fma.rn.f32x2 %0, %1, %2, %3;" : "=l"(d) : "l"(a), "l"(b), "l"(d));
}
__device__ __forceinline__ float2 upk2(unsigned long long v) {
    float2 f;
    asm("mov.b64 {%0, %1}, %2;" : "=f"(f.x), "=f"(f.y) : "l"(v));
    return f;
}

__device__ __forceinline__ float sigmoidf_(float x) {
    return 1.0f / (1.0f + expf(-x));
}

// Multi-value butterfly: reduce acc[0..15] (one per batch) across 32 lanes
// with 16 shfls. Afterwards lane pairs hold in acc[0] the full sum for
// batch (lane>>1)&15; even lanes are the designated writers.
__device__ __forceinline__ void butterfly16(float (&acc)[B_], int lane) {
    #pragma unroll
    for (int off = 16; off >= 2; off >>= 1) {
        const int nv = off >> 1;
        const bool hi = (lane & off) != 0;
        #pragma unroll
        for (int j = 0; j < nv; j++) {
            float send = hi ? acc[j] : acc[j + nv];
            float recv = __shfl_xor_sync(0xffffffffu, send, off);
            acc[j] = (hi ? acc[j + nv] : acc[j]) + recv;
        }
    }
    acc[0] += __shfl_xor_sync(0xffffffffu, acc[0], 1);
}

// ---------------- kernel 1: per-plane pools ------------------------------
__global__ void __launch_bounds__(192) pool_kernel(const float* __restrict__ X) {
    const int c = blockIdx.x;
    const int b = blockIdx.y;
    const float* plane = X + ((b * C_ + c) * H_) * (long)W_;

    const int tid  = threadIdx.x;
    const int warp = tid >> 5;
    const int lane = tid & 31;

    __shared__ float scs[6][W_];
    __shared__ float swt[6];

    float col0 = 0.f, col1 = 0.f, col2 = 0.f, col3 = 0.f, col4 = 0.f, col5 = 0.f;
    float tot = 0.f;

    const int h0 = warp * 32;
    for (int i = 0; i < 32; i++) {
        const int h = h0 + i;
        const float* row = plane + h * W_;
        float v0 = row[lane +   0];
        float v1 = row[lane +  32];
        float v2 = row[lane +  64];
        float v3 = row[lane +  96];
        float v4 = row[lane + 128];
        float v5 = row[lane + 160];
        col0 += v0; col1 += v1; col2 += v2; col3 += v3; col4 += v4; col5 += v5;
        float rs = ((v0 + v1) + (v2 + v3)) + (v4 + v5);
        #pragma unroll
        for (int off = 16; off >= 1; off >>= 1)
            rs += __shfl_down_sync(0xffffffffu, rs, off);
        if (lane == 0) {
            g_RS[(b * C_ + c) * H_ + h] = rs;
            tot += rs;
        }
    }
    scs[warp][lane +   0] = col0;
    scs[warp][lane +  32] = col1;
    scs[warp][lane +  64] = col2;
    scs[warp][lane +  96] = col3;
    scs[warp][lane + 128] = col4;
    scs[warp][lane + 160] = col5;
    if (lane == 0) swt[warp] = tot;
    __syncthreads();

    float cs = 0.f;
    #pragma unroll
    for (int j = 0; j < 6; j++) cs += scs[j][tid];
    g_CS[(b * C_ + c) * W_ + tid] = cs;

    if (tid == 0) {
        float t = 0.f;
        #pragma unroll
        for (int j = 0; j < 6; j++) t += swt[j];
        g_cp[b * C_ + c] = t * (1.0f / (H_ * (float)W_));
    }
}

// ---------------- kernel 2: reduce RS/CS over c -> hp, wp ----------------
__global__ void hw_pool_kernel() {
    const int i = blockIdx.x * blockDim.x + threadIdx.x;  // 0 .. B*H-1
    if (i >= B_ * H_) return;
    const int b = i / H_;
    const int h = i - b * H_;
    float s1 = 0.f, s2 = 0.f;
    for (int c = 0; c < C_; c++) {
        s1 += g_RS[(b * C_ + c) * H_ + h];
        s2 += g_CS[(b * C_ + c) * W_ + h];
    }
    g_hp[i] = s1 * (1.0f / (C_ * (float)W_));
    g_wp[i] = s2 * (1.0f / (C_ * (float)H_));
}

// ---------------- kernel 3: H/W sigmoid weights, warp-per-2-rows GEMV ----
// blockIdx.y: 0 = H branch (Wh,bh -> g_Hw), 1 = W branch (Ww,bw -> g_Ww).
// Each warp owns TWO consecutive rows m0,m1 of the [12288 x 192] weight
// matrix: sp LDS values are reused across both rows (12 FMA per 6 LDS),
// 12 LDG in flight for MLP, two 16-shfl butterflies.
__global__ void __launch_bounds__(256) rhw_weights_kernel(
        const float* __restrict__ Wh, const float* __restrict__ bh,
        const float* __restrict__ Wwp, const float* __restrict__ bw) {
    const int tid  = threadIdx.x;
    const int warp = tid >> 5;
    const int lane = tid & 31;
    const int m0   = blockIdx.x * 16 + warp * 2;   // 0..12286, step 2
    const int m1   = m0 + 1;
    const int wbranch = blockIdx.y;

    __shared__ float sp[B_][H_];
    {
        const float* pool = wbranch ? g_wp : g_hp;
        for (int i = tid; i < B_ * H_; i += 256)
            sp[i / H_][i - (i / H_) * H_] = pool[i];
    }
    __syncthreads();

    const float* Wsrc = wbranch ? Wwp : Wh;
    const float* bsrc = wbranch ? bw  : bh;
    const float* wrow0 = Wsrc + (long)m0 * H_;
    const float* wrow1 = Wsrc + (long)m1 * H_;

    float wa[6], wb[6];
    #pragma unroll
    for (int k = 0; k < 6; k++) wa[k] = wrow0[lane + 32 * k];
    #pragma unroll
    for (int k = 0; k < 6; k++) wb[k] = wrow1[lane + 32 * k];

    float acc0[B_], acc1[B_];
    #pragma unroll
    for (int b = 0; b < B_; b++) {
        float s0 = wa[0] * sp[b][lane];
        float s1 = wb[0] * sp[b][lane];
        #pragma unroll
        for (int k = 1; k < 6; k++) {
            const float pv = sp[b][lane + 32 * k];
            s0 = fmaf(wa[k], pv, s0);
            s1 = fmaf(wb[k], pv, s1);
        }
        acc0[b] = s0;
        acc1[b] = s1;
    }
    butterfly16(acc0, lane);
    butterfly16(acc1, lane);

    if ((lane & 1) == 0) {
        const int batch = lane >> 1;
        const int r0 = m0 / H_, d0 = m0 - r0 * H_;
        const int r1 = m1 / H_, d1 = m1 - r1 * H_;
        const float v0 = sigmoidf_(acc0[0] + bsrc[m0]);
        const float v1 = sigmoidf_(acc1[0] + bsrc[m1]);
        if (wbranch == 0) {
            g_Hw[(batch * H_ + d0) * R_ + r0] = v0;   // [B][H][R]
            g_Hw[(batch * H_ + d1) * R_ + r1] = v1;
        } else {
            g_Ww[(batch * R_ + r0) * W_ + d0] = v0;   // [B][R][W]
            g_Ww[(batch * R_ + r1) * W_ + d1] = v1;
        }
    }
}

// ---------------- kernel 3c: T[b][r][c] = p[r]*sigmoid(Wc@cp+bc) ---------
__global__ void __launch_bounds__(256) cw_kernel(
        const float* __restrict__ Wc, const float* __restrict__ bc,
        const float* __restrict__ p) {
    const int tid  = threadIdx.x;
    const int warp = tid >> 5;
    const int lane = tid & 31;
    const int m    = blockIdx.x * 8 + warp;   // 0..4095
    const int r    = m / C_;
    const int d    = m - r * C_;

    __shared__ float sp[B_][C_];
    for (int i = tid; i < B_ * C_; i += 256)
        sp[i >> 6][i & 63] = g_cp[i];
    __syncthreads();

    const float* wrow = Wc + m * C_;
    const float wv0 = wrow[lane];
    const float wv1 = wrow[lane + 32];

    float acc[B_];
    #pragma unroll
    for (int b = 0; b < B_; b++)
        acc[b] = fmaf(wv1, sp[b][lane + 32], wv0 * sp[b][lane]);
    butterfly16(acc, lane);

    if ((lane & 1) == 0) {
        const int batch = lane >> 1;
        const float v = p[r] * sigmoidf_(acc[0] + bc[m]);
        g_T[(batch * R_ + r) * C_ + d] = v;           // [B][R][C]
    }
}

// ---------------- kernel 4: main fused GEMM + elementwise ----------------
// Block = (h, w-half, b). Smem: M[r][c] = T[b][r][c]*Hw[b][h][r] (64x64),
// V[r][w'] = Ww[b][r][half*96 + w'] (64x96). Each of 192 threads owns an
// 8c x 4w register tile. M rows are loaded as ulonglong2 (same addresses
// as the float4 version, but f32x2 pairs arrive pre-packed: zero MOVs for
// the A operand; only 4 V-splat MOVs per r remain).
__global__ void __launch_bounds__(192) main_kernel(const float* __restrict__ X,
                                                   float* __restrict__ out) {
    const int h    = blockIdx.x;   // 0..191
    const int half = blockIdx.y;   // 0..1
    const int b    = blockIdx.z;   // 0..15

    const int tid = threadIdx.x;
    const int tc  = tid / 24;      // 0..7
    const int tw  = tid - tc * 24; // 0..23

    __shared__ __align__(16) float sM[R_ * C_];   // 16 KB  [r][c]
    __shared__ __align__(16) float sV[R_ * 96];   // 24 KB  [r][w']
    __shared__ float sh[R_];

    if (tid < R_) sh[tid] = g_Hw[(b * H_ + h) * R_ + tid];
    __syncthreads();

    // fill M = T * hw   (T layout [B][R][C], coalesced float4)
    {
        const float4* T4  = (const float4*)(g_T + b * (R_ * C_));
        float4*       sM4 = (float4*)sM;
        for (int i = tid; i < (R_ * C_) / 4; i += 192) {
            float4 t = T4[i];
            const float hv = sh[i >> 4];  // r = i / (C_/4)
            t.x *= hv; t.y *= hv; t.z *= hv; t.w *= hv;
            sM4[i] = t;
        }
    }
    // fill V half
    {
        float4* sV4 = (float4*)sV;
        for (int i = tid; i < R_ * 24; i += 192) {
            const int r = i / 24;
            const int j = i - r * 24;
            sV4[r * 24 + j] =
                ((const float4*)(g_Ww + (b * R_ + r) * W_ + half * 96))[j];
        }
    }
    __syncthreads();

    const ulonglong2* sM2 = (const ulonglong2*)sM;  // 16 per row of 64 floats
    const float4*     sV4 = (const float4*)sV;

    unsigned long long acc[4][4];  // [c-pair][w]
    #pragma unroll
    for (int i = 0; i < 4; i++)
        #pragma unroll
        for (int j = 0; j < 4; j++) acc[i][j] = 0ull;

    #pragma unroll 8
    for (int r = 0; r < R_; r++) {
        const ulonglong2 m0 = sM2[r * 16 + tc];      // c = 4tc..4tc+3 (2 pairs)
        const ulonglong2 m1 = sM2[r * 16 + 8 + tc];  // c = 32+4tc..+3
        const float4     bv = sV4[r * 24 + tw];      // w = 4tw..4tw+3

        const unsigned long long Bx = pk2(bv.x, bv.x);
        const unsigned long long By = pk2(bv.y, bv.y);
        const unsigned long long Bz = pk2(bv.z, bv.z);
        const unsigned long long Bw = pk2(bv.w, bv.w);

        fma2(acc[0][0], m0.x, Bx); fma2(acc[0][1], m0.x, By);
        fma2(acc[0][2], m0.x, Bz); fma2(acc[0][3], m0.x, Bw);
        fma2(acc[1][0], m0.y, Bx); fma2(acc[1][1], m0.y, By);
        fma2(acc[1][2], m0.y, Bz); fma2(acc[1][3], m0.y, Bw);
        fma2(acc[2][0], m1.x, Bx); fma2(acc[2][1], m1.x, By);
        fma2(acc[2][2], m1.x, Bz); fma2(acc[2][3], m1.x, Bw);
        fma2(acc[3][0], m1.y, Bx); fma2(acc[3][1], m1.y, By);
        fma2(acc[3][2], m1.y, Bz); fma2(acc[3][3], m1.y, Bw);
    }

    // unpack: vals[ci][wj], ci: 0..3 -> c = 4tc+ci ; 4..7 -> c = 32+4tc+(ci-4)
    float vals[8][4];
    #pragma unroll
    for (int cp = 0; cp < 4; cp++) {
        #pragma unroll
        for (int wj = 0; wj < 4; wj++) {
            const float2 q = upk2(acc[cp][wj]);
            vals[2 * cp + 0][wj] = q.x;
            vals[2 * cp + 1][wj] = q.y;
        }
    }

    const int w0 = half * 96 + tw * 4;
    #pragma unroll
    for (int ci = 0; ci < 8; ci++) {
        const int c = (ci < 4) ? (tc * 4 + ci) : (32 + tc * 4 + (ci - 4));
        const int idx = ((b * C_ + c) * H_ + h) * W_ + w0;
        const float4 x = *(const float4*)(X + idx);
        float4 o;
        o.x = vals[ci][0] * x.x;
        o.y = vals[ci][1] * x.y;
        o.z = vals[ci][2] * x.z;
        o.w = vals[ci][3] * x.w;
        *(float4*)(out + idx) = o;
    }
}

// ---------------- launch ---------------------------------------------------
extern "C" void kernel_launch(void* const* d_in, const int* in_sizes, int n_in,
                              void* d_out, int out_size) {
    const float* X   = (const float*)d_in[0];
    const float* p   = (const float*)d_in[1];
    const float* Wc  = (const float*)d_in[2];
    const float* bc  = (const float*)d_in[3];
    const float* Wh  = (const float*)d_in[4];
    const float* bh  = (const float*)d_in[5];
    const float* Wwp = (const float*)d_in[6];
    const float* bw  = (const float*)d_in[7];
    float* out = (float*)d_out;

    pool_kernel<<<dim3(C_, B_), 192>>>(X);
    hw_pool_kernel<<<(B_ * H_ + 255) / 256, 256>>>();
    cw_kernel<<<(R_ * C_) / 8, 256>>>(Wc, bc, p);
    rhw_weights_kernel<<<dim3((R_ * H_) / 16, 2), 256>>>(Wh, bh, Wwp, bw);
    main_kernel<<<dim3(H_, 2, B_), 192>>>(X, out);
}